// round 7
// baseline (speedup 1.0000x reference)
#include <cuda_runtime.h>
#include <cstdint>

// FSQCodebook: out[n] = sum_k (round(tanh(x[n,:]·W[k,:] + b[k]) * SCALE) + 1) * 3^k
// x: (65536, 1280) f32, W: (8, 1280) f32, b: (8) f32, out: 65536 (stored as f32)
//
// Mapping: warp = 4 row-groups x 8 lanes. Lane (sub, l) owns row (warp*4+sub)
// and K-slice columns c = l*4 + 32*i, i = 0..39. W LDS is 4-way broadcast
// across row-groups (free); acc is 8 packed f32x2 per thread.

#define NDIM_ 8
#define KDIM_ 1280
#define THREADS_ 512
#define WARPS_ (THREADS_ / 32)            // 16
#define ROWS_PER_BLOCK (WARPS_ * 4)       // 64
#define NROWS_ 65536
#define SCALE_F 0.9990000128746033f

typedef unsigned long long ull;

__device__ __forceinline__ void ffma2(ull& d, ull a, ull b) {
    asm volatile("fma.rn.f32x2 %0, %1, %2, %0;" : "+l"(d) : "l"(a), "l"(b));
}
__device__ __forceinline__ ull add2(ull a, ull b) {
    ull d;
    asm("add.rn.f32x2 %0, %1, %2;" : "=l"(d) : "l"(a), "l"(b));
    return d;
}
__device__ __forceinline__ float pairsum(ull v) {
    float lo, hi;
    asm("mov.b64 {%0, %1}, %2;" : "=f"(lo), "=f"(hi) : "l"(v));
    return lo + hi;
}

__global__ __launch_bounds__(THREADS_, 2)
void fsq_kernel(const float* __restrict__ x,
                const float* __restrict__ W,
                const float* __restrict__ b,
                float* __restrict__ out) {
    __shared__ __align__(16) float Wsm[NDIM_ * KDIM_];   // 40 KB
    __shared__ float bsm[NDIM_];

    const int tid = threadIdx.x;

    // Stage W into shared memory (2560 float4 / 512 threads = 5 each)
    {
        const float4* Wg = reinterpret_cast<const float4*>(W);
        float4* Ws = reinterpret_cast<float4*>(Wsm);
        #pragma unroll
        for (int i = 0; i < (NDIM_ * KDIM_ / 4) / THREADS_; ++i)
            Ws[i * THREADS_ + tid] = Wg[i * THREADS_ + tid];
    }
    if (tid < NDIM_) bsm[tid] = b[tid];
    __syncthreads();

    const int warp = tid >> 5;
    const int lane = tid & 31;
    const int sub  = lane >> 3;          // row-group within warp (0..3)
    const int l    = lane & 7;           // K-slice lane (0..7)
    const int row  = blockIdx.x * ROWS_PER_BLOCK + warp * 4 + sub;

    const float* xr = x + (size_t)row * KDIM_ + l * 4;
    const float* Wl = Wsm + l * 4;

    // acc[k] = packed (even-col partial, odd-col partial) for dim k
    ull acc[NDIM_];
    #pragma unroll
    for (int k = 0; k < NDIM_; ++k) acc[k] = 0ull;

    // 40 column-steps of 32 floats; prefetch 2 deep for MLP.
    #pragma unroll 2
    for (int i = 0; i < KDIM_ / 32; i += 2) {
        const ulonglong2 xv0 = *reinterpret_cast<const ulonglong2*>(xr + (i + 0) * 32);
        const ulonglong2 xv1 = *reinterpret_cast<const ulonglong2*>(xr + (i + 1) * 32);

        #pragma unroll
        for (int k = 0; k < NDIM_; ++k) {
            const ulonglong2 wv =
                *reinterpret_cast<const ulonglong2*>(Wl + k * KDIM_ + (i + 0) * 32);
            ffma2(acc[k], xv0.x, wv.x);
            ffma2(acc[k], xv0.y, wv.y);
        }
        #pragma unroll
        for (int k = 0; k < NDIM_; ++k) {
            const ulonglong2 wv =
                *reinterpret_cast<const ulonglong2*>(Wl + k * KDIM_ + (i + 1) * 32);
            ffma2(acc[k], xv1.x, wv.x);
            ffma2(acc[k], xv1.y, wv.y);
        }
    }

    // Reduce across the 8 lanes of this row-group (packed butterfly, 3 levels).
    #pragma unroll
    for (int k = 0; k < NDIM_; ++k) {
        ull v = acc[k];
        v = add2(v, __shfl_xor_sync(0xffffffffu, v, 4));
        v = add2(v, __shfl_xor_sync(0xffffffffu, v, 2));
        v = add2(v, __shfl_xor_sync(0xffffffffu, v, 1));
        acc[k] = v;
    }

    // Epilogue (valid on l == 0; other lanes compute garbage, don't store).
    float mu = 0.0f, p = 1.0f;
    #pragma unroll
    for (int k = 0; k < NDIM_; ++k) {
        float h = pairsum(acc[k]) + bsm[k];
        float t = tanhf(h) * SCALE_F;
        float q = rintf(t) + 1.0f;      // ternary {0,1,2}
        mu = fmaf(q, p, mu);
        p *= 3.0f;
    }
    if (l == 0)
        out[row] = mu;                   // 0..6560 exact in fp32
}

extern "C" void kernel_launch(void* const* d_in, const int* in_sizes, int n_in,
                              void* d_out, int out_size) {
    // Bind inputs by element count (robust to metadata ordering):
    //   x: 65536*1280 = 83886080, W: 8*1280 = 10240, b: 8
    const float* x = nullptr;
    const float* W = nullptr;
    const float* b = nullptr;
    for (int i = 0; i < n_in; ++i) {
        if (in_sizes[i] == NROWS_ * KDIM_)      x = (const float*)d_in[i];
        else if (in_sizes[i] == NDIM_ * KDIM_)  W = (const float*)d_in[i];
        else if (in_sizes[i] == NDIM_)          b = (const float*)d_in[i];
    }
    float* out = (float*)d_out;
    (void)out_size;

    const int blocks = NROWS_ / ROWS_PER_BLOCK;   // 1024
    fsq_kernel<<<blocks, THREADS_>>>(x, W, b, out);
}

// round 11
// speedup vs baseline: 1.4004x; 1.4004x over previous
#include <cuda_runtime.h>
#include <cstdint>

// FSQCodebook: out[n] = sum_k (round(tanh(x[n,:]·W[k,:] + b[k]) * SCALE) + 1) * 3^k
// x: (65536, 1280) f32, W: (8, 1280) f32, b: (8) f32, out: 65536 (stored as f32)
//
// R5 mapping (warp = 4 rows, lane covers cols lane*4 + 128*i) + software-
// pipelined x loads and NON-volatile FMA asm so loads overlap the FMA wall.

#define NDIM_ 8
#define KDIM_ 1280
#define ROWS_PER_WARP 4
#define THREADS_ 256
#define WARPS_ (THREADS_ / 32)
#define ROWS_PER_BLOCK (ROWS_PER_WARP * WARPS_)   // 32
#define NROWS_ 65536
#define NITER_ (KDIM_ / 128)                      // 10
#define SCALE_F 0.9990000128746033f

typedef unsigned long long ull;

// Pure arithmetic: NOT volatile, so ptxas may schedule loads across it.
__device__ __forceinline__ void ffma2(ull& d, ull a, ull b) {
    asm("fma.rn.f32x2 %0, %1, %2, %0;" : "+l"(d) : "l"(a), "l"(b));
}
__device__ __forceinline__ float pairsum(ull v) {
    float lo, hi;
    asm("mov.b64 {%0, %1}, %2;" : "=f"(lo), "=f"(hi) : "l"(v));
    return lo + hi;
}

__global__ __launch_bounds__(THREADS_, 2)
void fsq_kernel(const float* __restrict__ x,
                const float* __restrict__ W,
                const float* __restrict__ b,
                float* __restrict__ out) {
    __shared__ __align__(16) float Wsm[NDIM_ * KDIM_];   // 40 KB
    __shared__ float bsm[NDIM_];

    const int tid = threadIdx.x;

    // Stage W into shared memory (2560 float4 / 256 threads = 10 each)
    {
        const float4* Wg = reinterpret_cast<const float4*>(W);
        float4* Ws = reinterpret_cast<float4*>(Wsm);
        #pragma unroll
        for (int i = 0; i < (NDIM_ * KDIM_ / 4) / THREADS_; ++i)
            Ws[i * THREADS_ + tid] = Wg[i * THREADS_ + tid];
    }
    if (tid < NDIM_) bsm[tid] = b[tid];
    __syncthreads();

    const int warp = tid >> 5;
    const int lane = tid & 31;
    const int row0 = blockIdx.x * ROWS_PER_BLOCK + warp * ROWS_PER_WARP;
    const float* xrow = x + (size_t)row0 * KDIM_ + lane * 4;
    const float* Wl   = Wsm + lane * 4;

    // Packed f32x2 accumulators: [row][dim]
    ull acc[ROWS_PER_WARP][NDIM_];
    #pragma unroll
    for (int r = 0; r < ROWS_PER_WARP; ++r)
        #pragma unroll
        for (int k = 0; k < NDIM_; ++k)
            acc[r][k] = 0ull;

    // Software pipeline: prefetch iteration i+1's x while doing iteration i's FMAs.
    ulonglong2 cur[ROWS_PER_WARP];
    #pragma unroll
    for (int r = 0; r < ROWS_PER_WARP; ++r)
        cur[r] = *reinterpret_cast<const ulonglong2*>(xrow + r * KDIM_);

    #pragma unroll
    for (int i = 0; i < NITER_; ++i) {
        ulonglong2 nxt[ROWS_PER_WARP];
        if (i + 1 < NITER_) {
            #pragma unroll
            for (int r = 0; r < ROWS_PER_WARP; ++r)
                nxt[r] = *reinterpret_cast<const ulonglong2*>(
                             xrow + r * KDIM_ + (i + 1) * 128);
        }

        #pragma unroll
        for (int k = 0; k < NDIM_; ++k) {
            const ulonglong2 wv =
                *reinterpret_cast<const ulonglong2*>(Wl + k * KDIM_ + i * 128);
            #pragma unroll
            for (int r = 0; r < ROWS_PER_WARP; ++r) {
                ffma2(acc[r][k], cur[r].x, wv.x);
                ffma2(acc[r][k], cur[r].y, wv.y);
            }
        }

        if (i + 1 < NITER_) {
            #pragma unroll
            for (int r = 0; r < ROWS_PER_WARP; ++r)
                cur[r] = nxt[r];
        }
    }

    // Reduce across the warp; lane r (< ROWS_PER_WARP) keeps row r's result.
    float h[NDIM_];
    #pragma unroll
    for (int k = 0; k < NDIM_; ++k) h[k] = 0.0f;

    #pragma unroll
    for (int r = 0; r < ROWS_PER_WARP; ++r) {
        #pragma unroll
        for (int k = 0; k < NDIM_; ++k) {
            float s = pairsum(acc[r][k]);
            #pragma unroll
            for (int off = 16; off > 0; off >>= 1)
                s += __shfl_xor_sync(0xffffffffu, s, off);
            if (lane == r) h[k] = s + bsm[k];
        }
    }

    // Epilogue: lanes 0..3 hold valid h; all lanes execute, 4 write.
    float mu = 0.0f, p = 1.0f;
    #pragma unroll
    for (int k = 0; k < NDIM_; ++k) {
        float t = tanhf(h[k]) * SCALE_F;
        float q = rintf(t) + 1.0f;      // ternary {0,1,2}
        mu = fmaf(q, p, mu);
        p *= 3.0f;
    }
    if (lane < ROWS_PER_WARP)
        out[row0 + lane] = mu;          // 0..6560 exact in fp32

}

extern "C" void kernel_launch(void* const* d_in, const int* in_sizes, int n_in,
                              void* d_out, int out_size) {
    // Bind inputs by element count (robust to metadata ordering):
    //   x: 65536*1280 = 83886080, W: 8*1280 = 10240, b: 8
    const float* x = nullptr;
    const float* W = nullptr;
    const float* b = nullptr;
    for (int i = 0; i < n_in; ++i) {
        if (in_sizes[i] == NROWS_ * KDIM_)      x = (const float*)d_in[i];
        else if (in_sizes[i] == NDIM_ * KDIM_)  W = (const float*)d_in[i];
        else if (in_sizes[i] == NDIM_)          b = (const float*)d_in[i];
    }
    float* out = (float*)d_out;
    (void)out_size;

    const int blocks = NROWS_ / ROWS_PER_BLOCK;   // 2048
    fsq_kernel<<<blocks, THREADS_>>>(x, W, b, out);
}

// round 12
// speedup vs baseline: 1.4434x; 1.0307x over previous
#include <cuda_runtime.h>
#include <cstdint>

// FSQCodebook: out[n] = sum_k (round(tanh(x[n,:]·W[k,:] + b[k]) * SCALE) + 1) * 3^k
// x: (65536, 1280) f32, W: (8, 1280) f32, b: (8) f32, out: 65536 (stored as f32)
//
// Warp = 4 rows. W is pre-packed in smem as u64 k-pairs: Wp[kp][c] =
// (W[2kp][c], W[2kp+1][c]); one FFMA2 accumulates two dims of one column, so
// acc[row][kp] = 16 u64 = 32 regs -> 3 CTAs/SM.
// Lane owns columns {2l, 2l+1, 64+2l, 64+2l+1} of each 128-col block:
// W LDS.128 lane stride = 16 B (conflict-free); x LDG.64 fully coalesced.

#define NDIM_ 8
#define KP_ 4                              // k-pairs
#define KDIM_ 1280
#define ROWS_PER_WARP 4
#define THREADS_ 256
#define WARPS_ (THREADS_ / 32)
#define ROWS_PER_BLOCK (ROWS_PER_WARP * WARPS_)   // 32
#define NROWS_ 65536
#define NITER_ (KDIM_ / 128)               // 10
#define SCALE_F 0.9990000128746033f

typedef unsigned long long ull;

__device__ __forceinline__ void ffma2(ull& d, ull a, ull b) {
    asm("fma.rn.f32x2 %0, %1, %2, %0;" : "+l"(d) : "l"(a), "l"(b));
}
__device__ __forceinline__ ull add2(ull a, ull b) {
    ull d;
    asm("add.rn.f32x2 %0, %1, %2;" : "=l"(d) : "l"(a), "l"(b));
    return d;
}
__device__ __forceinline__ ull dup2(float v) {
    ull d;
    asm("mov.b64 %0, {%1, %1};" : "=l"(d) : "f"(v));
    return d;
}
__device__ __forceinline__ ull packf2(float lo, float hi) {
    ull d;
    asm("mov.b64 %0, {%1, %2};" : "=l"(d) : "f"(lo), "f"(hi));
    return d;
}
__device__ __forceinline__ void unpack2(ull v, float& lo, float& hi) {
    asm("mov.b64 {%0, %1}, %2;" : "=f"(lo), "=f"(hi) : "l"(v));
}

__global__ __launch_bounds__(THREADS_, 3)
void fsq_kernel(const float* __restrict__ x,
                const float* __restrict__ W,
                const float* __restrict__ b,
                float* __restrict__ out) {
    __shared__ __align__(16) ull Wp[KP_ * KDIM_];   // 40 KB packed k-pairs
    __shared__ float bsm[NDIM_];

    const int tid = threadIdx.x;

    // Stage W packed: Wp[kp*KDIM + c] = (W[2kp][c], W[2kp+1][c]).
    // idx = i*256+tid: within each i, kp is constant and c is contiguous
    // (1280 % 256 == 0) -> coalesced LDG of both W rows.
    #pragma unroll
    for (int i = 0; i < (KP_ * KDIM_) / THREADS_; ++i) {     // 20
        const int idx = i * THREADS_ + tid;
        const int kp = idx / KDIM_;
        const int c  = idx - kp * KDIM_;
        Wp[idx] = packf2(W[(2 * kp) * KDIM_ + c], W[(2 * kp + 1) * KDIM_ + c]);
    }
    if (tid < NDIM_) bsm[tid] = b[tid];
    __syncthreads();

    const int warp = tid >> 5;
    const int lane = tid & 31;
    const int row0 = blockIdx.x * ROWS_PER_BLOCK + warp * ROWS_PER_WARP;
    const float* xr = x + (size_t)row0 * KDIM_ + lane * 2;

    // acc[r][kp]: lo accumulates dim 2kp, hi accumulates dim 2kp+1 (32 regs).
    ull acc[ROWS_PER_WARP][KP_];
    #pragma unroll
    for (int r = 0; r < ROWS_PER_WARP; ++r)
        #pragma unroll
        for (int kp = 0; kp < KP_; ++kp)
            acc[r][kp] = 0ull;

    #pragma unroll
    for (int i = 0; i < NITER_; ++i) {
        // x: lane's 2 column-pairs per row: cols i*128 + {2l,2l+1} and +64.
        float2 xa[ROWS_PER_WARP], xb[ROWS_PER_WARP];
        #pragma unroll
        for (int r = 0; r < ROWS_PER_WARP; ++r) {
            xa[r] = *reinterpret_cast<const float2*>(xr + r * KDIM_ + i * 128);
            xb[r] = *reinterpret_cast<const float2*>(xr + r * KDIM_ + i * 128 + 64);
        }

        // Broadcast each x value into both halves (16 packs).
        ull x0[ROWS_PER_WARP], x1[ROWS_PER_WARP], x2[ROWS_PER_WARP], x3[ROWS_PER_WARP];
        #pragma unroll
        for (int r = 0; r < ROWS_PER_WARP; ++r) {
            x0[r] = dup2(xa[r].x);  x1[r] = dup2(xa[r].y);
            x2[r] = dup2(xb[r].x);  x3[r] = dup2(xb[r].y);
        }

        #pragma unroll
        for (int kp = 0; kp < KP_; ++kp) {
            // Conflict-free LDS.128: lane stride 16 B within each 128 B row.
            const ulonglong2 wA = *reinterpret_cast<const ulonglong2*>(
                Wp + kp * KDIM_ + i * 128 + lane * 2);
            const ulonglong2 wB = *reinterpret_cast<const ulonglong2*>(
                Wp + kp * KDIM_ + i * 128 + 64 + lane * 2);
            #pragma unroll
            for (int r = 0; r < ROWS_PER_WARP; ++r) {
                ffma2(acc[r][kp], x0[r], wA.x);
                ffma2(acc[r][kp], x1[r], wA.y);
                ffma2(acc[r][kp], x2[r], wB.x);
                ffma2(acc[r][kp], x3[r], wB.y);
            }
        }
    }

    // Warp reduction (packed butterfly); lane r keeps row r's 4 k-pairs.
    ull hp[KP_];
    #pragma unroll
    for (int kp = 0; kp < KP_; ++kp) hp[kp] = 0ull;

    #pragma unroll
    for (int r = 0; r < ROWS_PER_WARP; ++r) {
        #pragma unroll
        for (int kp = 0; kp < KP_; ++kp) {
            ull v = acc[r][kp];
            #pragma unroll
            for (int off = 16; off > 0; off >>= 1)
                v = add2(v, __shfl_xor_sync(0xffffffffu, v, off));
            if (lane == r) hp[kp] = v;
        }
    }

    // Epilogue: lanes 0..3 hold valid hp; all lanes execute, 4 write.
    float mu = 0.0f, p = 1.0f;
    #pragma unroll
    for (int kp = 0; kp < KP_; ++kp) {
        float hlo, hhi;
        unpack2(hp[kp], hlo, hhi);
        {
            float t = tanhf(hlo + bsm[2 * kp]) * SCALE_F;
            mu = fmaf(rintf(t) + 1.0f, p, mu);
            p *= 3.0f;
        }
        {
            float t = tanhf(hhi + bsm[2 * kp + 1]) * SCALE_F;
            mu = fmaf(rintf(t) + 1.0f, p, mu);
            p *= 3.0f;
        }
    }
    if (lane < ROWS_PER_WARP)
        out[row0 + lane] = mu;          // 0..6560 exact in fp32
}

extern "C" void kernel_launch(void* const* d_in, const int* in_sizes, int n_in,
                              void* d_out, int out_size) {
    // Bind inputs by element count (robust to metadata ordering):
    //   x: 65536*1280 = 83886080, W: 8*1280 = 10240, b: 8
    const float* x = nullptr;
    const float* W = nullptr;
    const float* b = nullptr;
    for (int i = 0; i < n_in; ++i) {
        if (in_sizes[i] == NROWS_ * KDIM_)      x = (const float*)d_in[i];
        else if (in_sizes[i] == NDIM_ * KDIM_)  W = (const float*)d_in[i];
        else if (in_sizes[i] == NDIM_)          b = (const float*)d_in[i];
    }
    float* out = (float*)d_out;
    (void)out_size;

    const int blocks = NROWS_ / ROWS_PER_BLOCK;   // 2048
    fsq_kernel<<<blocks, THREADS_>>>(x, W, b, out);
}